// round 16
// baseline (speedup 1.0000x reference)
#include <cuda_runtime.h>
#include <cuda_fp16.h>
#include <cstdint>

#define B_  2
#define L_  4096
#define D_  1024
#define H_  16
#define W_  512
#define C_  8
#define M_  (B_ * L_)

// Scratch (device globals: allocation-free per harness rules)
__device__ __half g_xh[M_ * D_];        // x rounded to f16
__device__ __half g_wh[4 * D_ * D_];    // Wq,Wk,Wv,Wo rounded to f16
__device__ __half g_qh[M_ * D_];        // q * 0.125*log2e, f16
__device__ __half g_kh[M_ * D_];        // k, f16
__device__ __half g_vt[M_ * D_];        // v transposed: [b][h][d][token]
__device__ __half g_ah[M_ * D_];        // attention out, f16

// ---------------------------------------------------------------------------
// helpers
// ---------------------------------------------------------------------------
__device__ __forceinline__ float ex2(float x) {
    float y;
    asm("ex2.approx.ftz.f32 %0, %1;" : "=f"(y) : "f"(x));
    return y;
}
__device__ __forceinline__ uint32_t smem_u32(const void* p) {
    uint32_t a;
    asm("{ .reg .u64 t; cvta.to.shared.u64 t, %1; cvt.u32.u64 %0, t; }"
        : "=r"(a) : "l"(p));
    return a;
}
__device__ __forceinline__ void cp_async16(uint32_t dst, const void* src) {
    asm volatile("cp.async.cg.shared.global [%0], [%1], 16;" :: "r"(dst), "l"(src));
}
#define CP_COMMIT()  asm volatile("cp.async.commit_group;" ::: "memory")
#define CP_WAIT(n)   asm volatile("cp.async.wait_group %0;" :: "n"(n) : "memory")

__device__ __forceinline__ uint32_t h2pack(float lo, float hi) {
    __half2 h = __floats2half2_rn(lo, hi);
    return *(uint32_t*)&h;
}

// ldmatrix x4: 4 8x8 b16 matrices, lane i supplies row address
__device__ __forceinline__ void ldsm4(uint32_t* r, uint32_t a) {
    asm volatile("ldmatrix.sync.aligned.m8n8.x4.shared.b16 {%0,%1,%2,%3}, [%4];"
        : "=r"(r[0]), "=r"(r[1]), "=r"(r[2]), "=r"(r[3]) : "r"(a));
}

// D += A*B, m16n8k16 f16, f32 accum
__device__ __forceinline__ void mma16(float* d, const uint32_t* a, const uint32_t* b) {
    asm volatile(
        "mma.sync.aligned.m16n8k16.row.col.f32.f16.f16.f32 "
        "{%0,%1,%2,%3}, {%4,%5,%6,%7}, {%8,%9}, {%0,%1,%2,%3};"
        : "+f"(d[0]), "+f"(d[1]), "+f"(d[2]), "+f"(d[3])
        : "r"(a[0]), "r"(a[1]), "r"(a[2]), "r"(a[3]), "r"(b[0]), "r"(b[1]));
}

// ---------------------------------------------------------------------------
// Pre-pass: x and 4x W -> f16 once.
// ---------------------------------------------------------------------------
__global__ __launch_bounds__(256) void cvt_all(
    const float* __restrict__ x,
    const float* __restrict__ w0, const float* __restrict__ w1,
    const float* __restrict__ w2, const float* __restrict__ w3) {
    const int XN8 = M_ * D_ / 8;
    const int WN8 = D_ * D_ / 8;
    const int total = XN8 + 4 * WN8;
    for (int i = blockIdx.x * 256 + threadIdx.x; i < total; i += gridDim.x * 256) {
        const float4* src;
        __half* dst;
        if (i < XN8) { src = (const float4*)x + 2 * i; dst = g_xh + 8 * i; }
        else {
            int r = i - XN8, wsel = r / WN8, off = r % WN8;
            const float* ws = wsel == 0 ? w0 : wsel == 1 ? w1 : wsel == 2 ? w2 : w3;
            src = (const float4*)ws + 2 * off;
            dst = g_wh + (size_t)wsel * D_ * D_ + 8 * off;
        }
        float4 v0 = src[0], v1 = src[1];
        uint32_t o[4];
        o[0] = h2pack(v0.x, v0.y); o[1] = h2pack(v0.z, v0.w);
        o[2] = h2pack(v1.x, v1.y); o[3] = h2pack(v1.z, v1.w);
        *(uint4*)dst = *(uint4*)o;
    }
}

// ---------------------------------------------------------------------------
// f16 mma.sync GEMM with ldmatrix operand fetch.
// 256 threads, tile 128x128, BK=32 f16, 5-stage cp.async ring, 1 sync/iter.
// smem rows padded to 20 b32 (LDSM: 8 rows stride-20 cover all 32 banks).
// mode: 0 fp32 out, 1 f16 (k), 2 f16 scaled (q), 3 f16 transposed (v->g_vt).
// ---------------------------------------------------------------------------
#define KSTR 20                     // b32 per smem row
#define NSTG 5
#define GEMM_SMEM (NSTG * 2 * 128 * KSTR * 4)   // 102400 B
#define QSCALE (0.125f * 1.4426950408889634f)

__device__ __forceinline__ void gemm_f16_body(
    const __half* __restrict__ A, const __half* __restrict__ Bw,
    const float* __restrict__ bias, void* __restrict__ outp, int mode) {
    extern __shared__ float smem_f[];
    uint32_t* As = (uint32_t*)smem_f;             // [NSTG][128][20]
    uint32_t* Bs = As + NSTG * 128 * KSTR;
    const uint32_t sA = smem_u32(As), sB = smem_u32(Bs);

    const int tid  = threadIdx.x;
    const int lane = tid & 31;
    const int warp = tid >> 5;
    const int g = lane >> 2, t = lane & 3;
    const int bm = blockIdx.y * 128;
    const int bn = blockIdx.x * 128;
    const int wm = (warp & 1) * 64;
    const int wn = (warp >> 1) * 32;

    // LDSM per-lane base offsets (b32 units within one stage buffer)
    const int l8 = lane & 7;
    const uint32_t aOff = (uint32_t)((wm + l8 + ((lane >> 3) & 1) * 8) * KSTR
                                     + (lane >> 4) * 4);
    const uint32_t bOff = (uint32_t)((wn + l8 + (lane >> 4) * 8) * KSTR
                                     + ((lane >> 3) & 1) * 4);

    float acc[4][4][4];
#pragma unroll
    for (int mi = 0; mi < 4; mi++)
#pragma unroll
        for (int nj = 0; nj < 4; nj++)
#pragma unroll
            for (int e = 0; e < 4; e++) acc[mi][nj][e] = 0.f;

#define ISSUE(j, stg)                                                          \
    {                                                                          \
        _Pragma("unroll")                                                      \
        for (int p = 0; p < 2; p++) {                                          \
            int s_ = tid + p * 256;                                            \
            int r_ = s_ >> 2, c4_ = s_ & 3;                                    \
            uint32_t off = (uint32_t)(((stg) * 128 + r_) * KSTR + c4_ * 4) * 4;\
            cp_async16(sA + off, &A[(size_t)(bm + r_) * D_ + (j) * 32 + c4_ * 8]); \
            cp_async16(sB + off, &Bw[(size_t)(bn + r_) * D_ + (j) * 32 + c4_ * 8]); \
        }                                                                      \
    }

    ISSUE(0, 0); CP_COMMIT();
    ISSUE(1, 1); CP_COMMIT();
    ISSUE(2, 2); CP_COMMIT();
    ISSUE(3, 3); CP_COMMIT();

    const int NIT = D_ / 32;   // 32 iters
    for (int j = 0; j < NIT; j++) {
        const int stg = j % NSTG;
        CP_WAIT(3);            // stage j done (groups complete in order)
        __syncthreads();       // all warps finished reading the reused buffer
        if (j + 4 < NIT) { ISSUE(j + 4, (j + 4) % NSTG); }
        CP_COMMIT();           // empty commits keep group counting uniform

        const uint32_t baseA = sA + (uint32_t)(stg * 128 * KSTR) * 4;
        const uint32_t baseB = sB + (uint32_t)(stg * 128 * KSTR) * 4;
#pragma unroll
        for (int ks = 0; ks < 2; ks++) {
            uint32_t af[4][4];
#pragma unroll
            for (int mi = 0; mi < 4; mi++)
                ldsm4(af[mi], baseA + (aOff + mi * 16 * KSTR + ks * 8) * 4);
            uint32_t bfp[2][4];
#pragma unroll
            for (int np = 0; np < 2; np++)
                ldsm4(bfp[np], baseB + (bOff + np * 16 * KSTR + ks * 8) * 4);
#pragma unroll
            for (int nj = 0; nj < 4; nj++) {
                const uint32_t* bf = &bfp[nj >> 1][(nj & 1) * 2];
#pragma unroll
                for (int mi = 0; mi < 4; mi++) mma16(acc[mi][nj], af[mi], bf);
            }
        }
    }

    if (mode == 0) {
        float* Cout = (float*)outp;
#pragma unroll
        for (int mi = 0; mi < 4; mi++)
#pragma unroll
            for (int nj = 0; nj < 4; nj++) {
                const int col = bn + wn + nj * 8 + 2 * t;
                const float bx = bias[col], by = bias[col + 1];
                const int r0 = bm + wm + mi * 16 + g;
                float2 v0 = { acc[mi][nj][0] + bx, acc[mi][nj][1] + by };
                float2 v1 = { acc[mi][nj][2] + bx, acc[mi][nj][3] + by };
                *(float2*)&Cout[(size_t)r0 * D_ + col] = v0;
                *(float2*)&Cout[(size_t)(r0 + 8) * D_ + col] = v1;
            }
    } else if (mode == 3) {
        // V: transpose through smem, then coalesced f16 stores to g_vt.
        __syncthreads();
        __half* Tt = (__half*)smem_f;   // [128 d-cols][136 tokens-padded]
#pragma unroll
        for (int mi = 0; mi < 4; mi++)
#pragma unroll
            for (int nj = 0; nj < 4; nj++) {
                const int cl = wn + nj * 8 + 2 * t;
                const float bx = bias[bn + cl], by = bias[bn + cl + 1];
                const int r0 = wm + mi * 16 + g;
                Tt[cl * 136 + r0]       = __float2half_rn(acc[mi][nj][0] + bx);
                Tt[(cl + 1) * 136 + r0] = __float2half_rn(acc[mi][nj][1] + by);
                Tt[cl * 136 + r0 + 8]       = __float2half_rn(acc[mi][nj][2] + bx);
                Tt[(cl + 1) * 136 + r0 + 8] = __float2half_rn(acc[mi][nj][3] + by);
            }
        __syncthreads();
        const int bb = bm >> 12;           // batch
        const int tok0 = bm & (L_ - 1);
        // 128 d-cols x 128 tokens = 2048 float4 units (16 per d-col)
#pragma unroll
        for (int p = 0; p < 8; p++) {
            int i = tid + p * 256;
            int row = i >> 4, f4 = i & 15;
            const int gc = bn + row;
            const int hh = gc >> 6, dl = gc & 63;
            float4 v = *(float4*)&Tt[row * 136 + f4 * 8];
            *(float4*)&g_vt[((size_t)((bb * H_ + hh) * 64 + dl)) * L_ + tok0 + f4 * 8] = v;
        }
    } else {
        const float sc = (mode == 2) ? QSCALE : 1.f;
        __half* Cout = (mode == 2) ? g_qh : g_kh;
#pragma unroll
        for (int mi = 0; mi < 4; mi++)
#pragma unroll
            for (int nj = 0; nj < 4; nj++) {
                const int col = bn + wn + nj * 8 + 2 * t;
                const float bx = bias[col], by = bias[col + 1];
                const int r0 = bm + wm + mi * 16 + g;
                uint32_t v0 = h2pack((acc[mi][nj][0] + bx) * sc, (acc[mi][nj][1] + by) * sc);
                uint32_t v1 = h2pack((acc[mi][nj][2] + bx) * sc, (acc[mi][nj][3] + by) * sc);
                *(uint32_t*)&Cout[(size_t)r0 * D_ + col] = v0;
                *(uint32_t*)&Cout[(size_t)(r0 + 8) * D_ + col] = v1;
            }
    }
#undef ISSUE
}

__global__ __launch_bounds__(256, 2) void gemm_qkv_f16(
    const float* __restrict__ bq, const float* __restrict__ bk,
    const float* __restrict__ bv) {
    const __half* Wt = g_wh + (size_t)blockIdx.z * D_ * D_;
    const float* bias;
    int mode;
    if (blockIdx.z == 0)      { bias = bq; mode = 2; }
    else if (blockIdx.z == 1) { bias = bk; mode = 1; }
    else                      { bias = bv; mode = 3; }
    gemm_f16_body(g_xh, Wt, bias, nullptr, mode);
}

__global__ __launch_bounds__(256, 2) void gemm_out_f16(
    const float* __restrict__ bo, float* __restrict__ out) {
    gemm_f16_body(g_ah, g_wh + (size_t)3 * D_ * D_, bo, out, 0);
}

// ---------------------------------------------------------------------------
// Sliding-window flash attention, f16 mma + ldmatrix, 256 threads.
// (Exact R14 structure: 2-stage KV double buffer, two syncs per tile.)
// Ks [key][d] stride 36 b32; Vt [d][token] stride 36 b32 (LDSM conflict-free).
// P: C-frag == A-frag in f16 -> zero shuffles.
// ---------------------------------------------------------------------------
#define AKSTR 36
#define ATTN_SMEM (2 * 2 * 64 * AKSTR * 4)   // 36864 B

__global__ __launch_bounds__(256) void attn_f16() {
    extern __shared__ float smem_f[];
    uint32_t* Ks = (uint32_t*)smem_f;           // [2][64][36]
    uint32_t* Vs = Ks + 2 * 64 * AKSTR;         // [2][64][36]
    const uint32_t sK = smem_u32(Ks), sV = smem_u32(Vs);

    const int tid  = threadIdx.x;
    const int lane = tid & 31;
    const int warp = tid >> 5;
    const int g = lane >> 2, t = lane & 3;
    const int qt = blockIdx.x;            // 0..3
    const int h  = blockIdx.y;
    const int b  = blockIdx.z >> 3;
    const int c  = blockIdx.z & 7;
    const int qrow0 = b * L_ + c * W_ + qt * 128 + warp * 16;

    // LDSM per-lane base offset (b32 units): rows n0-7/n8-15, k halves 0/8
    const int l8 = lane & 7;
    const uint32_t fOff = (uint32_t)((l8 + (lane >> 4) * 8) * AKSTR
                                     + ((lane >> 3) & 1) * 4);

    // Q a-frags (scale pre-folded into g_qh). b32 view: 512 per row.
    const uint32_t* q32 = (const uint32_t*)g_qh;
    uint32_t qf[4][4];
#pragma unroll
    for (int ks = 0; ks < 4; ks++) {
        const int cc = h * 32 + ks * 8 + t;
        qf[ks][0] = q32[(size_t)(qrow0 + g) * 512 + cc];
        qf[ks][1] = q32[(size_t)(qrow0 + g + 8) * 512 + cc];
        qf[ks][2] = q32[(size_t)(qrow0 + g) * 512 + cc + 4];
        qf[ks][3] = q32[(size_t)(qrow0 + g + 8) * 512 + cc + 4];
    }

    float of[8][4];
    float mrow[2] = { -1e30f, -1e30f }, lrow[2] = { 0.f, 0.f };
#pragma unroll
    for (int nj = 0; nj < 8; nj++)
#pragma unroll
        for (int e = 0; e < 4; e++) of[nj][e] = 0.f;

    const __half* kh = g_kh;
    const size_t vtbase = (size_t)(b * H_ + h) * 64 * L_;

    auto issueKV = [&](int kt, int buf) {
        const int tok = (c - 1) * W_ + kt * 64;
#pragma unroll
        for (int p = 0; p < 2; p++) {
            int s_ = tid + p * 256;
            int r_ = s_ >> 3, c4_ = s_ & 7;   // 8 x 16B per 64-wide f16 row
            uint32_t off = (uint32_t)((buf * 64 + r_) * AKSTR + c4_ * 4) * 4;
            cp_async16(sK + off, &kh[(size_t)(b * L_ + tok + r_) * D_ + h * 64 + c4_ * 8]);
            cp_async16(sV + off, &g_vt[vtbase + (size_t)r_ * L_ + tok + c4_ * 8]);
        }
    };

    const int kt0 = (c == 0) ? 8 : 0;   // chunk 0 lookback is padding
    issueKV(kt0, 0); CP_COMMIT();
    for (int kt = kt0; kt < 16; kt++) {
        const int buf = (kt - kt0) & 1;
        if (kt + 1 < 16) { issueKV(kt + 1, buf ^ 1); CP_COMMIT(); CP_WAIT(1); }
        else             { CP_WAIT(0); }
        __syncthreads();

        const uint32_t baseK = sK + (uint32_t)(buf * 64 * AKSTR) * 4;
        const uint32_t baseV = sV + (uint32_t)(buf * 64 * AKSTR) * 4;

        // S = Q @ K^T
        float s[8][4];
#pragma unroll
        for (int nj = 0; nj < 8; nj++)
#pragma unroll
            for (int e = 0; e < 4; e++) s[nj][e] = 0.f;
#pragma unroll
        for (int ks = 0; ks < 4; ks++) {
#pragma unroll
            for (int np = 0; np < 4; np++) {
                uint32_t bfp[4];
                ldsm4(bfp, baseK + (fOff + np * 16 * AKSTR + ks * 8) * 4);
                mma16(s[np * 2],     qf[ks], &bfp[0]);
                mma16(s[np * 2 + 1], qf[ks], &bfp[2]);
            }
        }

        // Online softmax (base-2; row = quad of 4 lanes)
#pragma unroll
        for (int hh = 0; hh < 2; hh++) {
            const int e0 = hh * 2;
            float mx = -1e30f;
#pragma unroll
            for (int nj = 0; nj < 8; nj++)
                mx = fmaxf(mx, fmaxf(s[nj][e0], s[nj][e0 + 1]));
            mx = fmaxf(mx, __shfl_xor_sync(0xffffffffu, mx, 1));
            mx = fmaxf(mx, __shfl_xor_sync(0xffffffffu, mx, 2));
            const float mnew = fmaxf(mrow[hh], mx);
            const float corr = ex2(mrow[hh] - mnew);
            float rs = 0.f;
#pragma unroll
            for (int nj = 0; nj < 8; nj++) {
                float p0 = ex2(s[nj][e0] - mnew);
                float p1 = ex2(s[nj][e0 + 1] - mnew);
                s[nj][e0] = p0; s[nj][e0 + 1] = p1;
                rs += p0 + p1;
                of[nj][e0] *= corr;
                of[nj][e0 + 1] *= corr;
            }
            rs += __shfl_xor_sync(0xffffffffu, rs, 1);
            rs += __shfl_xor_sync(0xffffffffu, rs, 2);
            lrow[hh] = lrow[hh] * corr + rs;
            mrow[hh] = mnew;
        }

        // O += P @ V: pack adjacent S tiles into f16 A-frags (no shuffles)
#pragma unroll
        for (int kk = 0; kk < 4; kk++) {
            uint32_t am[4];
            am[0] = h2pack(s[2 * kk][0], s[2 * kk][1]);
            am[1] = h2pack(s[2 * kk][2], s[2 * kk][3]);
            am[2] = h2pack(s[2 * kk + 1][0], s[2 * kk + 1][1]);
            am[3] = h2pack(s[2 * kk + 1][2], s[2 * kk + 1][3]);
#pragma unroll
            for (int np = 0; np < 4; np++) {
                uint32_t bfp[4];
                ldsm4(bfp, baseV + (fOff + np * 16 * AKSTR + kk * 8) * 4);
                mma16(of[np * 2],     am, &bfp[0]);
                mma16(of[np * 2 + 1], am, &bfp[2]);
            }
        }
        __syncthreads();
    }

    // Epilogue: normalize, f16 store to g_ah
    const float inv0 = 1.f / lrow[0];
    const float inv1 = 1.f / lrow[1];
#pragma unroll
    for (int nj = 0; nj < 8; nj++) {
        const int col = h * 64 + nj * 8 + 2 * t;
        uint32_t v0 = h2pack(of[nj][0] * inv0, of[nj][1] * inv0);
        uint32_t v1 = h2pack(of[nj][2] * inv1, of[nj][3] * inv1);
        *(uint32_t*)&g_ah[(size_t)(qrow0 + g) * D_ + col] = v0;
        *(uint32_t*)&g_ah[(size_t)(qrow0 + g + 8) * D_ + col] = v1;
    }
}

// ---------------------------------------------------------------------------
extern "C" void kernel_launch(void* const* d_in, const int* in_sizes, int n_in,
                              void* d_out, int out_size) {
    const float* x  = (const float*)d_in[0];
    const float* Wq = (const float*)d_in[1];
    const float* bq = (const float*)d_in[2];
    const float* Wk = (const float*)d_in[3];
    const float* bk = (const float*)d_in[4];
    const float* Wv = (const float*)d_in[5];
    const float* bv = (const float*)d_in[6];
    const float* Wo = (const float*)d_in[7];
    const float* bo = (const float*)d_in[8];
    float* out = (float*)d_out;

    cudaFuncSetAttribute(gemm_qkv_f16, cudaFuncAttributeMaxDynamicSharedMemorySize, GEMM_SMEM);
    cudaFuncSetAttribute(gemm_out_f16, cudaFuncAttributeMaxDynamicSharedMemorySize, GEMM_SMEM);
    cudaFuncSetAttribute(attn_f16, cudaFuncAttributeMaxDynamicSharedMemorySize, ATTN_SMEM);

    cvt_all<<<1024, 256>>>(x, Wq, Wk, Wv, Wo);
    gemm_qkv_f16<<<dim3(D_ / 128, M_ / 128, 3), 256, GEMM_SMEM>>>(bq, bk, bv);
    attn_f16<<<dim3(4, H_, B_ * C_), 256, ATTN_SMEM>>>();
    gemm_out_f16<<<dim3(D_ / 128, M_ / 128), 256, GEMM_SMEM>>>(bo, out);
}

// round 17
// speedup vs baseline: 1.4853x; 1.4853x over previous
#include <cuda_runtime.h>
#include <cuda_fp16.h>
#include <cstdint>

#define B_  2
#define L_  4096
#define D_  1024
#define H_  16
#define W_  512
#define C_  8
#define M_  (B_ * L_)

// Scratch (device globals: allocation-free per harness rules)
__device__ __half g_xh[M_ * D_];        // x rounded to f16
__device__ __half g_wh[4 * D_ * D_];    // Wq,Wk,Wv,Wo rounded to f16
__device__ __half g_qh[M_ * D_];        // q * 0.125*log2e, f16
__device__ __half g_kh[M_ * D_];        // k, f16
__device__ __half g_vt[M_ * D_];        // v transposed: [b][h][d][token]
__device__ __half g_ah[M_ * D_];        // attention out, f16

// ---------------------------------------------------------------------------
// helpers
// ---------------------------------------------------------------------------
__device__ __forceinline__ float ex2(float x) {
    float y;
    asm("ex2.approx.ftz.f32 %0, %1;" : "=f"(y) : "f"(x));
    return y;
}
__device__ __forceinline__ uint32_t smem_u32(const void* p) {
    uint32_t a;
    asm("{ .reg .u64 t; cvta.to.shared.u64 t, %1; cvt.u32.u64 %0, t; }"
        : "=r"(a) : "l"(p));
    return a;
}
__device__ __forceinline__ void cp_async16(uint32_t dst, const void* src) {
    asm volatile("cp.async.cg.shared.global [%0], [%1], 16;" :: "r"(dst), "l"(src));
}
#define CP_COMMIT()  asm volatile("cp.async.commit_group;" ::: "memory")
#define CP_WAIT(n)   asm volatile("cp.async.wait_group %0;" :: "n"(n) : "memory")

__device__ __forceinline__ uint32_t h2pack(float lo, float hi) {
    __half2 h = __floats2half2_rn(lo, hi);
    return *(uint32_t*)&h;
}

// ldmatrix x4: 4 8x8 b16 matrices, lane i supplies row address
__device__ __forceinline__ void ldsm4(uint32_t* r, uint32_t a) {
    asm volatile("ldmatrix.sync.aligned.m8n8.x4.shared.b16 {%0,%1,%2,%3}, [%4];"
        : "=r"(r[0]), "=r"(r[1]), "=r"(r[2]), "=r"(r[3]) : "r"(a));
}

// D += A*B, m16n8k16 f16, f32 accum
__device__ __forceinline__ void mma16(float* d, const uint32_t* a, const uint32_t* b) {
    asm volatile(
        "mma.sync.aligned.m16n8k16.row.col.f32.f16.f16.f32 "
        "{%0,%1,%2,%3}, {%4,%5,%6,%7}, {%8,%9}, {%0,%1,%2,%3};"
        : "+f"(d[0]), "+f"(d[1]), "+f"(d[2]), "+f"(d[3])
        : "r"(a[0]), "r"(a[1]), "r"(a[2]), "r"(a[3]), "r"(b[0]), "r"(b[1]));
}

// ---------------------------------------------------------------------------
// Pre-pass: x and 4x W -> f16 once.
// ---------------------------------------------------------------------------
__global__ __launch_bounds__(256) void cvt_all(
    const float* __restrict__ x,
    const float* __restrict__ w0, const float* __restrict__ w1,
    const float* __restrict__ w2, const float* __restrict__ w3) {
    const int XN8 = M_ * D_ / 8;
    const int WN8 = D_ * D_ / 8;
    const int total = XN8 + 4 * WN8;
    for (int i = blockIdx.x * 256 + threadIdx.x; i < total; i += gridDim.x * 256) {
        const float4* src;
        __half* dst;
        if (i < XN8) { src = (const float4*)x + 2 * i; dst = g_xh + 8 * i; }
        else {
            int r = i - XN8, wsel = r / WN8, off = r % WN8;
            const float* ws = wsel == 0 ? w0 : wsel == 1 ? w1 : wsel == 2 ? w2 : w3;
            src = (const float4*)ws + 2 * off;
            dst = g_wh + (size_t)wsel * D_ * D_ + 8 * off;
        }
        float4 v0 = src[0], v1 = src[1];
        uint32_t o[4];
        o[0] = h2pack(v0.x, v0.y); o[1] = h2pack(v0.z, v0.w);
        o[2] = h2pack(v1.x, v1.y); o[3] = h2pack(v1.z, v1.w);
        *(uint4*)dst = *(uint4*)o;
    }
}

// ---------------------------------------------------------------------------
// f16 mma.sync GEMM with ldmatrix operand fetch.
// 256 threads, tile 128x128, BK=32 f16, 4-stage cp.async, 1 sync/iter.
// smem rows padded to 20 b32 (LDSM: 8 rows stride-20 cover all 32 banks).
// mode: 0 fp32 out, 1 f16 (k), 2 f16 scaled (q), 3 f16 transposed (v->g_vt).
// ---------------------------------------------------------------------------
#define KSTR 20                     // b32 per smem row
#define GEMM_SMEM (4 * 2 * 128 * KSTR * 4)   // 81920 B
#define QSCALE (0.125f * 1.4426950408889634f)

__device__ __forceinline__ void gemm_f16_body(
    const __half* __restrict__ A, const __half* __restrict__ Bw,
    const float* __restrict__ bias, void* __restrict__ outp, int mode) {
    extern __shared__ float smem_f[];
    uint32_t* As = (uint32_t*)smem_f;             // [4][128][20]
    uint32_t* Bs = As + 4 * 128 * KSTR;
    const uint32_t sA = smem_u32(As), sB = smem_u32(Bs);

    const int tid  = threadIdx.x;
    const int lane = tid & 31;
    const int warp = tid >> 5;
    const int g = lane >> 2, t = lane & 3;
    const int bm = blockIdx.y * 128;
    const int bn = blockIdx.x * 128;
    const int wm = (warp & 1) * 64;
    const int wn = (warp >> 1) * 32;

    // LDSM per-lane base offsets (b32 units within one stage buffer)
    const int l8 = lane & 7;
    const uint32_t aOff = (uint32_t)((wm + l8 + ((lane >> 3) & 1) * 8) * KSTR
                                     + (lane >> 4) * 4);
    const uint32_t bOff = (uint32_t)((wn + l8 + (lane >> 4) * 8) * KSTR
                                     + ((lane >> 3) & 1) * 4);

    float acc[4][4][4];
#pragma unroll
    for (int mi = 0; mi < 4; mi++)
#pragma unroll
        for (int nj = 0; nj < 4; nj++)
#pragma unroll
            for (int e = 0; e < 4; e++) acc[mi][nj][e] = 0.f;

#define ISSUE(j, stg)                                                          \
    {                                                                          \
        _Pragma("unroll")                                                      \
        for (int p = 0; p < 2; p++) {                                          \
            int s_ = tid + p * 256;                                            \
            int r_ = s_ >> 2, c4_ = s_ & 3;                                    \
            uint32_t off = (uint32_t)(((stg) * 128 + r_) * KSTR + c4_ * 4) * 4;\
            cp_async16(sA + off, &A[(size_t)(bm + r_) * D_ + (j) * 32 + c4_ * 8]); \
            cp_async16(sB + off, &Bw[(size_t)(bn + r_) * D_ + (j) * 32 + c4_ * 8]); \
        }                                                                      \
    }

    ISSUE(0, 0); CP_COMMIT();
    ISSUE(1, 1); CP_COMMIT();
    ISSUE(2, 2); CP_COMMIT();

    const int NIT = D_ / 32;   // 32 iters
    for (int j = 0; j < NIT; j++) {
        const int stg = j & 3;
        CP_WAIT(2);
        __syncthreads();
        if (j + 3 < NIT) { ISSUE(j + 3, (j + 3) & 3); }
        CP_COMMIT();

        const uint32_t baseA = sA + (uint32_t)(stg * 128 * KSTR) * 4;
        const uint32_t baseB = sB + (uint32_t)(stg * 128 * KSTR) * 4;
#pragma unroll
        for (int ks = 0; ks < 2; ks++) {
            uint32_t af[4][4];
#pragma unroll
            for (int mi = 0; mi < 4; mi++)
                ldsm4(af[mi], baseA + (aOff + mi * 16 * KSTR + ks * 8) * 4);
            uint32_t bfp[2][4];
#pragma unroll
            for (int np = 0; np < 2; np++)
                ldsm4(bfp[np], baseB + (bOff + np * 16 * KSTR + ks * 8) * 4);
#pragma unroll
            for (int nj = 0; nj < 4; nj++) {
                const uint32_t* bf = &bfp[nj >> 1][(nj & 1) * 2];
#pragma unroll
                for (int mi = 0; mi < 4; mi++) mma16(acc[mi][nj], af[mi], bf);
            }
        }
    }

    if (mode == 0) {
        float* Cout = (float*)outp;
#pragma unroll
        for (int mi = 0; mi < 4; mi++)
#pragma unroll
            for (int nj = 0; nj < 4; nj++) {
                const int col = bn + wn + nj * 8 + 2 * t;
                const float bx = bias[col], by = bias[col + 1];
                const int r0 = bm + wm + mi * 16 + g;
                float2 v0 = { acc[mi][nj][0] + bx, acc[mi][nj][1] + by };
                float2 v1 = { acc[mi][nj][2] + bx, acc[mi][nj][3] + by };
                *(float2*)&Cout[(size_t)r0 * D_ + col] = v0;
                *(float2*)&Cout[(size_t)(r0 + 8) * D_ + col] = v1;
            }
    } else if (mode == 3) {
        // V: transpose through smem, then coalesced f16 stores to g_vt.
        __syncthreads();
        __half* Tt = (__half*)smem_f;   // [128 d-cols][136 tokens-padded]
#pragma unroll
        for (int mi = 0; mi < 4; mi++)
#pragma unroll
            for (int nj = 0; nj < 4; nj++) {
                const int cl = wn + nj * 8 + 2 * t;
                const float bx = bias[bn + cl], by = bias[bn + cl + 1];
                const int r0 = wm + mi * 16 + g;
                Tt[cl * 136 + r0]       = __float2half_rn(acc[mi][nj][0] + bx);
                Tt[(cl + 1) * 136 + r0] = __float2half_rn(acc[mi][nj][1] + by);
                Tt[cl * 136 + r0 + 8]       = __float2half_rn(acc[mi][nj][2] + bx);
                Tt[(cl + 1) * 136 + r0 + 8] = __float2half_rn(acc[mi][nj][3] + by);
            }
        __syncthreads();
        const int bb = bm >> 12;           // batch
        const int tok0 = bm & (L_ - 1);
        // 128 d-cols x 128 tokens = 2048 float4 units (16 per d-col)
#pragma unroll
        for (int p = 0; p < 8; p++) {
            int i = tid + p * 256;
            int row = i >> 4, f4 = i & 15;
            const int gc = bn + row;
            const int hh = gc >> 6, dl = gc & 63;
            float4 v = *(float4*)&Tt[row * 136 + f4 * 8];
            *(float4*)&g_vt[((size_t)((bb * H_ + hh) * 64 + dl)) * L_ + tok0 + f4 * 8] = v;
        }
    } else {
        const float sc = (mode == 2) ? QSCALE : 1.f;
        __half* Cout = (mode == 2) ? g_qh : g_kh;
#pragma unroll
        for (int mi = 0; mi < 4; mi++)
#pragma unroll
            for (int nj = 0; nj < 4; nj++) {
                const int col = bn + wn + nj * 8 + 2 * t;
                const float bx = bias[col], by = bias[col + 1];
                const int r0 = bm + wm + mi * 16 + g;
                uint32_t v0 = h2pack((acc[mi][nj][0] + bx) * sc, (acc[mi][nj][1] + by) * sc);
                uint32_t v1 = h2pack((acc[mi][nj][2] + bx) * sc, (acc[mi][nj][3] + by) * sc);
                *(uint32_t*)&Cout[(size_t)r0 * D_ + col] = v0;
                *(uint32_t*)&Cout[(size_t)(r0 + 8) * D_ + col] = v1;
            }
    }
#undef ISSUE
}

__global__ __launch_bounds__(256, 2) void gemm_qkv_f16(
    const float* __restrict__ bq, const float* __restrict__ bk,
    const float* __restrict__ bv) {
    const __half* Wt = g_wh + (size_t)blockIdx.z * D_ * D_;
    const float* bias;
    int mode;
    if (blockIdx.z == 0)      { bias = bq; mode = 2; }
    else if (blockIdx.z == 1) { bias = bk; mode = 1; }
    else                      { bias = bv; mode = 3; }
    gemm_f16_body(g_xh, Wt, bias, nullptr, mode);
}

__global__ __launch_bounds__(256, 2) void gemm_out_f16(
    const float* __restrict__ bo, float* __restrict__ out) {
    gemm_f16_body(g_ah, g_wh + (size_t)3 * D_ * D_, bo, out, 0);
}

// ---------------------------------------------------------------------------
// Sliding-window flash attention, f16 mma + ldmatrix, 256 threads.
// Ks [key][d] stride 36 b32; Vt [d][token] stride 36 b32 (LDSM conflict-free).
// P: C-frag == A-frag in f16 -> zero shuffles.
// ---------------------------------------------------------------------------
#define AKSTR 36
#define ATTN_SMEM (2 * 2 * 64 * AKSTR * 4)   // 36864 B

__global__ __launch_bounds__(256) void attn_f16() {
    extern __shared__ float smem_f[];
    uint32_t* Ks = (uint32_t*)smem_f;           // [2][64][36]
    uint32_t* Vs = Ks + 2 * 64 * AKSTR;         // [2][64][36]
    const uint32_t sK = smem_u32(Ks), sV = smem_u32(Vs);

    const int tid  = threadIdx.x;
    const int lane = tid & 31;
    const int warp = tid >> 5;
    const int g = lane >> 2, t = lane & 3;
    const int qt = blockIdx.x;            // 0..3
    const int h  = blockIdx.y;
    const int b  = blockIdx.z >> 3;
    const int c  = blockIdx.z & 7;
    const int qrow0 = b * L_ + c * W_ + qt * 128 + warp * 16;

    // LDSM per-lane base offset (b32 units): rows n0-7/n8-15, k halves 0/8
    const int l8 = lane & 7;
    const uint32_t fOff = (uint32_t)((l8 + (lane >> 4) * 8) * AKSTR
                                     + ((lane >> 3) & 1) * 4);

    // Q a-frags (scale pre-folded into g_qh). b32 view: 512 per row.
    const uint32_t* q32 = (const uint32_t*)g_qh;
    uint32_t qf[4][4];
#pragma unroll
    for (int ks = 0; ks < 4; ks++) {
        const int cc = h * 32 + ks * 8 + t;
        qf[ks][0] = q32[(size_t)(qrow0 + g) * 512 + cc];
        qf[ks][1] = q32[(size_t)(qrow0 + g + 8) * 512 + cc];
        qf[ks][2] = q32[(size_t)(qrow0 + g) * 512 + cc + 4];
        qf[ks][3] = q32[(size_t)(qrow0 + g + 8) * 512 + cc + 4];
    }

    float of[8][4];
    float mrow[2] = { -1e30f, -1e30f }, lrow[2] = { 0.f, 0.f };
#pragma unroll
    for (int nj = 0; nj < 8; nj++)
#pragma unroll
        for (int e = 0; e < 4; e++) of[nj][e] = 0.f;

    const __half* kh = g_kh;
    const size_t vtbase = (size_t)(b * H_ + h) * 64 * L_;

    auto issueKV = [&](int kt, int buf) {
        const int tok = (c - 1) * W_ + kt * 64;
#pragma unroll
        for (int p = 0; p < 2; p++) {
            int s_ = tid + p * 256;
            int r_ = s_ >> 3, c4_ = s_ & 7;   // 8 x 16B per 64-wide f16 row
            uint32_t off = (uint32_t)((buf * 64 + r_) * AKSTR + c4_ * 4) * 4;
            cp_async16(sK + off, &kh[(size_t)(b * L_ + tok + r_) * D_ + h * 64 + c4_ * 8]);
            cp_async16(sV + off, &g_vt[vtbase + (size_t)r_ * L_ + tok + c4_ * 8]);
        }
    };

    const int kt0 = (c == 0) ? 8 : 0;   // chunk 0 lookback is padding
    issueKV(kt0, 0); CP_COMMIT();
    for (int kt = kt0; kt < 16; kt++) {
        const int buf = (kt - kt0) & 1;
        if (kt + 1 < 16) { issueKV(kt + 1, buf ^ 1); CP_COMMIT(); CP_WAIT(1); }
        else             { CP_WAIT(0); }
        __syncthreads();

        const uint32_t baseK = sK + (uint32_t)(buf * 64 * AKSTR) * 4;
        const uint32_t baseV = sV + (uint32_t)(buf * 64 * AKSTR) * 4;

        // S = Q @ K^T
        float s[8][4];
#pragma unroll
        for (int nj = 0; nj < 8; nj++)
#pragma unroll
            for (int e = 0; e < 4; e++) s[nj][e] = 0.f;
#pragma unroll
        for (int ks = 0; ks < 4; ks++) {
#pragma unroll
            for (int np = 0; np < 4; np++) {
                uint32_t bfp[4];
                ldsm4(bfp, baseK + (fOff + np * 16 * AKSTR + ks * 8) * 4);
                mma16(s[np * 2],     qf[ks], &bfp[0]);
                mma16(s[np * 2 + 1], qf[ks], &bfp[2]);
            }
        }

        // Online softmax (base-2; row = quad of 4 lanes)
#pragma unroll
        for (int hh = 0; hh < 2; hh++) {
            const int e0 = hh * 2;
            float mx = -1e30f;
#pragma unroll
            for (int nj = 0; nj < 8; nj++)
                mx = fmaxf(mx, fmaxf(s[nj][e0], s[nj][e0 + 1]));
            mx = fmaxf(mx, __shfl_xor_sync(0xffffffffu, mx, 1));
            mx = fmaxf(mx, __shfl_xor_sync(0xffffffffu, mx, 2));
            const float mnew = fmaxf(mrow[hh], mx);
            const float corr = ex2(mrow[hh] - mnew);
            float rs = 0.f;
#pragma unroll
            for (int nj = 0; nj < 8; nj++) {
                float p0 = ex2(s[nj][e0] - mnew);
                float p1 = ex2(s[nj][e0 + 1] - mnew);
                s[nj][e0] = p0; s[nj][e0 + 1] = p1;
                rs += p0 + p1;
                of[nj][e0] *= corr;
                of[nj][e0 + 1] *= corr;
            }
            rs += __shfl_xor_sync(0xffffffffu, rs, 1);
            rs += __shfl_xor_sync(0xffffffffu, rs, 2);
            lrow[hh] = lrow[hh] * corr + rs;
            mrow[hh] = mnew;
        }

        // O += P @ V: pack adjacent S tiles into f16 A-frags (no shuffles)
#pragma unroll
        for (int kk = 0; kk < 4; kk++) {
            uint32_t am[4];
            am[0] = h2pack(s[2 * kk][0], s[2 * kk][1]);
            am[1] = h2pack(s[2 * kk][2], s[2 * kk][3]);
            am[2] = h2pack(s[2 * kk + 1][0], s[2 * kk + 1][1]);
            am[3] = h2pack(s[2 * kk + 1][2], s[2 * kk + 1][3]);
#pragma unroll
            for (int np = 0; np < 4; np++) {
                uint32_t bfp[4];
                ldsm4(bfp, baseV + (fOff + np * 16 * AKSTR + kk * 8) * 4);
                mma16(of[np * 2],     am, &bfp[0]);
                mma16(of[np * 2 + 1], am, &bfp[2]);
            }
        }
        __syncthreads();
    }

    // Epilogue: normalize, f16 store to g_ah
    const float inv0 = 1.f / lrow[0];
    const float inv1 = 1.f / lrow[1];
#pragma unroll
    for (int nj = 0; nj < 8; nj++) {
        const int col = h * 64 + nj * 8 + 2 * t;
        uint32_t v0 = h2pack(of[nj][0] * inv0, of[nj][1] * inv0);
        uint32_t v1 = h2pack(of[nj][2] * inv1, of[nj][3] * inv1);
        *(uint32_t*)&g_ah[(size_t)(qrow0 + g) * D_ + col] = v0;
        *(uint32_t*)&g_ah[(size_t)(qrow0 + g + 8) * D_ + col] = v1;
    }
}

// ---------------------------------------------------------------------------
extern "C" void kernel_launch(void* const* d_in, const int* in_sizes, int n_in,
                              void* d_out, int out_size) {
    const float* x  = (const float*)d_in[0];
    const float* Wq = (const float*)d_in[1];
    const float* bq = (const float*)d_in[2];
    const float* Wk = (const float*)d_in[3];
    const float* bk = (const float*)d_in[4];
    const float* Wv = (const float*)d_in[5];
    const float* bv = (const float*)d_in[6];
    const float* Wo = (const float*)d_in[7];
    const float* bo = (const float*)d_in[8];
    float* out = (float*)d_out;

    cudaFuncSetAttribute(gemm_qkv_f16, cudaFuncAttributeMaxDynamicSharedMemorySize, GEMM_SMEM);
    cudaFuncSetAttribute(gemm_out_f16, cudaFuncAttributeMaxDynamicSharedMemorySize, GEMM_SMEM);
    cudaFuncSetAttribute(attn_f16, cudaFuncAttributeMaxDynamicSharedMemorySize, ATTN_SMEM);

    cvt_all<<<1024, 256>>>(x, Wq, Wk, Wv, Wo);
    gemm_qkv_f16<<<dim3(D_ / 128, M_ / 128, 3), 256, GEMM_SMEM>>>(bq, bk, bv);
    attn_f16<<<dim3(4, H_, B_ * C_), 256, ATTN_SMEM>>>();
    gemm_out_f16<<<dim3(D_ / 128, M_ / 128), 256, GEMM_SMEM>>>(bo, out);
}